// round 17
// baseline (speedup 1.0000x reference)
#include <cuda_runtime.h>
#include <math.h>
#include <mma.h>

using namespace nvcuda;

#define NSZ 192
#define NC  16
#define MXY 32
#define NLINE (NC*NSZ)       // 3072
#define NROW  (NC*NSZ*NSZ)   // 589824

// ---------------- twiddle tables + scratch -----------------------------------
static __device__ float2 Tm[NSZ];             // (cos, sin) of 2*pi*p/192
static __device__ float Bzf[32 * 192];        // s1 B, col-major: Bzf[n*192+t]
static __device__ float Bif[192 * 32];        // i3 B, col-major: Bif[z*32+k]

static __device__ __align__(16) float2 X1g[(size_t)NROW * 16];            // (c,x,y,kz)
static __device__ __align__(16) float2 X2g[(size_t)NLINE * MXY * 16];     // (c,x,ky,kz)
static __device__ __align__(16) float2 X3g[(size_t)NC * MXY * MXY * 16];  // (i,kx,ky,kz)
static __device__ __align__(16) float2 Y3g[(size_t)NC * MXY * MXY * 16];  // (o,kx,ky,kz)
static __device__ __align__(16) float2 Y2g[(size_t)NLINE * MXY * 16];     // (c,x,ky,kz)
static __device__ __align__(16) float2 Y1g[(size_t)NROW * 16];            // (c,x,y,kz)

__device__ __forceinline__ int kmap(int j) { return j < 16 ? j : j + 160; }

__global__ void k_init() {
  int tid = threadIdx.x;
  const float TWO_PI = 6.283185307179586f;
  for (int p = tid; p < NSZ; p += 256) {
    float s, c;
    sincosf(TWO_PI * (float)p / 192.0f, &s, &c);
    Tm[p] = make_float2(c, s);
  }
  // s1 twiddle matrix: col n=2k -> cos(2pi k t/192); n=2k+1 -> -sin
  for (int i = tid; i < 32 * 192; i += 256) {
    int n = i / 192, t = i % 192;
    int k = n >> 1;
    float s, c;
    sincosf(TWO_PI * (float)((k * t) % NSZ) / 192.0f, &s, &c);
    Bzf[i] = (n & 1) ? -s : c;
  }
  // i3 matrix: row 2k -> a_k cos(2pi k z/192); row 2k+1 -> -a_k sin
  const float inv = 1.0f / (192.0f * 192.0f * 192.0f);
  for (int i = tid; i < 192 * 32; i += 256) {
    int z = i / 32, k2 = i % 32;
    int k = k2 >> 1;
    float a = (k == 0) ? inv : 2.0f * inv;
    float s, c;
    sincosf(TWO_PI * (float)((k * z) % NSZ) / 192.0f, &s, &c);
    Bif[i] = (k2 & 1) ? -a * s : a * c;
  }
}

// ---------------- S1: z-DFT as tf32 GEMM  X1 = x @ Bz ------------------------
// block: 256 thr = 8 warps (4 row-tiles x 2 col-tiles); 64 rows x 32 cols
__global__ void __launch_bounds__(256) k_s1(const float* __restrict__ xg) {
  __shared__ float Bs[32 * 192];                  // 24 KB, col-major
  __shared__ __align__(16) float As[64][40];      // 10.25 KB, k-chunk of 32
  int tid = threadIdx.x;
  int wid = tid >> 5;
  int wr = wid >> 1, wc = wid & 1;
  size_t rowBase = (size_t)blockIdx.x * 64;

  for (int i = tid; i < 32 * 192; i += 256) Bs[i] = Bzf[i];

  wmma::fragment<wmma::accumulator, 16, 16, 8, float> acc;
  wmma::fill_fragment(acc, 0.0f);

  for (int kc = 0; kc < 192; kc += 32) {
    __syncthreads();
    for (int i = tid; i < 512; i += 256) {
      int row = i >> 3, u = i & 7;
      ((float4*)&As[row][0])[u] =
          *(const float4*)(xg + (rowBase + row) * NSZ + kc + 4 * u);
    }
    __syncthreads();
#pragma unroll
    for (int k0 = 0; k0 < 32; k0 += 8) {
      wmma::fragment<wmma::matrix_a, 16, 16, 8, wmma::precision::tf32, wmma::row_major> af;
      wmma::fragment<wmma::matrix_b, 16, 16, 8, wmma::precision::tf32, wmma::col_major> bf;
      wmma::load_matrix_sync(af, &As[wr * 16][k0], 40);
      wmma::load_matrix_sync(bf, &Bs[(wc * 16) * 192 + kc + k0], 192);
#pragma unroll
      for (int t = 0; t < af.num_elements; t++) af.x[t] = wmma::__float_to_tf32(af.x[t]);
#pragma unroll
      for (int t = 0; t < bf.num_elements; t++) bf.x[t] = wmma::__float_to_tf32(bf.x[t]);
      wmma::mma_sync(acc, af, bf, acc);
    }
  }
  float* X1out = (float*)X1g;
  wmma::store_matrix_sync(X1out + (rowBase + wr * 16) * 32 + wc * 16, acc, 32,
                          wmma::mem_row_major);
}

// ---------------- S2: y-DFT, complex, 32 ky modes, folded (R14) --------------
__global__ void __launch_bounds__(128) k_s2() {
  __shared__ __align__(16) float2 sA[4][24][16];   // sum
  __shared__ __align__(16) float2 dA[4][24][16];   // diff
  __shared__ float2 twy[24][32];
  int tid = threadIdx.x;
  int l = tid >> 5, lane = tid & 31;
  int kyg = lane >> 2, kzg = lane & 3;
  int lineBase = blockIdx.x * 4;

  float2 acc[4][4];
#pragma unroll
  for (int a = 0; a < 4; a++)
#pragma unroll
    for (int b = 0; b < 4; b++) acc[a][b] = make_float2(0.f, 0.f);

  for (int yc = 0; yc < 96; yc += 24) {
    __syncthreads();
    for (int i = tid; i < 24 * 32; i += 128) {
      int yl = i >> 5, ky = i & 31;
      int p = (kmap(ky) * (yc + yl)) % NSZ;
      twy[yl][ky] = Tm[p];
    }
    for (int i = tid; i < 4 * 24 * 8; i += 128) {
      int li = i / 192, r = i % 192;
      int yl = r >> 3, u = r & 7;
      const float4* pa = (const float4*)&X1g[((size_t)(lineBase + li) * NSZ + yc + yl) * 16];
      const float4* pb = (const float4*)&X1g[((size_t)(lineBase + li) * NSZ + yc + 96 + yl) * 16];
      float4 a = pa[u], b = pb[u];
      ((float4*)&sA[li][yl][0])[u] = make_float4(a.x + b.x, a.y + b.y, a.z + b.z, a.w + b.w);
      ((float4*)&dA[li][yl][0])[u] = make_float4(a.x - b.x, a.y - b.y, a.z - b.z, a.w - b.w);
    }
    __syncthreads();
#pragma unroll 4
    for (int yl = 0; yl < 24; yl++) {
      float2 sv[4], dv[4];
      ((float4*)sv)[0] = ((float4*)&sA[l][yl][4 * kzg])[0];
      ((float4*)sv)[1] = ((float4*)&sA[l][yl][4 * kzg])[1];
      ((float4*)dv)[0] = ((float4*)&dA[l][yl][4 * kzg])[0];
      ((float4*)dv)[1] = ((float4*)&dA[l][yl][4 * kzg])[1];
#pragma unroll
      for (int a = 0; a < 4; a++) {
        float2 t = twy[yl][4 * kyg + a];
        const float2* v = (a & 1) ? dv : sv;   // ky parity = a parity
#pragma unroll
        for (int b = 0; b < 4; b++) {
          acc[a][b].x += t.x * v[b].x + t.y * v[b].y;
          acc[a][b].y += t.x * v[b].y - t.y * v[b].x;
        }
      }
    }
  }
#pragma unroll
  for (int a = 0; a < 4; a++) {
    size_t base = ((size_t)(lineBase + l) * MXY + 4 * kyg + a) * 16 + 4 * kzg;
    ((float4*)&X2g[base])[0] = make_float4(acc[a][0].x, acc[a][0].y, acc[a][1].x, acc[a][1].y);
    ((float4*)&X2g[base])[1] = make_float4(acc[a][2].x, acc[a][2].y, acc[a][3].x, acc[a][3].y);
  }
}

// ---------------- S3: x-DFT, complex, 32 kx modes, folded (R14) --------------
__global__ void __launch_bounds__(256) k_s3() {
  __shared__ __align__(16) float2 sA[96][16];
  __shared__ __align__(16) float2 dA[96][16];
  __shared__ float2 Tml[NSZ];
  int c = blockIdx.x >> 5, ky = blockIdx.x & 31;
  int tid = threadIdx.x;
  int kx = tid & 31, kzp = tid >> 5;

  for (int i = tid; i < NSZ; i += 256) Tml[i] = Tm[i];
  for (int i = tid; i < 96 * 8; i += 256) {
    int xx = i >> 3, u = i & 7;
    float4 a = ((const float4*)&X2g[(((size_t)c * NSZ + xx) * MXY + ky) * 16])[u];
    float4 b = ((const float4*)&X2g[(((size_t)c * NSZ + xx + 96) * MXY + ky) * 16])[u];
    ((float4*)&sA[xx][0])[u] = make_float4(a.x + b.x, a.y + b.y, a.z + b.z, a.w + b.w);
    ((float4*)&dA[xx][0])[u] = make_float4(a.x - b.x, a.y - b.y, a.z - b.z, a.w - b.w);
  }
  __syncthreads();

  const float2* vb = (kx & 1) ? &dA[0][0] : &sA[0][0];
  int kf = kmap(kx), p = 0;
  float2 a0 = make_float2(0.f, 0.f), a1 = make_float2(0.f, 0.f);
#pragma unroll 4
  for (int xx = 0; xx < 96; xx++) {
    float2 t = Tml[p];
    float4 v = *(const float4*)(vb + xx * 16 + 2 * kzp);
    a0.x += t.x * v.x + t.y * v.y;  a0.y += t.x * v.y - t.y * v.x;
    a1.x += t.x * v.z + t.y * v.w;  a1.y += t.x * v.w - t.y * v.z;
    p += kf; if (p >= NSZ) p -= NSZ;
  }
  size_t base = (((size_t)c * MXY + kx) * MXY + ky) * 16 + 2 * kzp;
  ((float4*)&X3g[base])[0] = make_float4(a0.x, a0.y, a1.x, a1.y);
}

// ---------------- Mix: per-mode 16x16 complex channel mix --------------------
__global__ void __launch_bounds__(256) k_mix(const float* __restrict__ wr,
                                             const float* __restrict__ wi) {
  __shared__ float2 xin[16][16];
  int kx = blockIdx.x >> 5, ky = blockIdx.x & 31;
  int tid = threadIdx.x;
  int kz = tid & 15, o = tid >> 4;
  {
    int i = tid >> 4, z = tid & 15;
    xin[i][z] = X3g[(((size_t)i * MXY + kx) * MXY + ky) * 16 + z];
  }
  __syncthreads();
  int q = (kx >= 16 ? 1 : 0) + (ky >= 16 ? 2 : 0);
  int mx = kx & 15, my = ky & 15;
  int moff = mx * 256 + my * 16 + kz;
  float2 acc = make_float2(0.f, 0.f);
#pragma unroll
  for (int i = 0; i < 16; i++) {
    int widx = ((q * 16 + i) * 16 + o) * 4096 + moff;
    float wrv = wr[widx], wiv = wi[widx];
    float2 xv = xin[i][kz];
    acc.x += xv.x * wrv - xv.y * wiv;
    acc.y += xv.x * wiv + xv.y * wrv;
  }
  Y3g[(((size_t)o * MXY + kx) * MXY + ky) * 16 + kz] = acc;
}

// ---------------- I1: inverse x (32 modes -> 192 x), even/odd folded ---------
__global__ void __launch_bounds__(192) k_i1() {
  __shared__ __align__(16) float2 ysd[2][32][16];
  __shared__ float2 Tml[NSZ];
  int c = blockIdx.x >> 4, kyp = blockIdx.x & 15;
  int tid = threadIdx.x;
  int h = tid / 96, x = tid % 96;
  int ky = 2 * kyp + h;

  for (int i = tid; i < NSZ; i += 192) Tml[i] = Tm[i];
  for (int i = tid; i < 1024; i += 192) {
    int hh = i >> 9, r = i & 511;
    ysd[hh][r >> 4][r & 15] =
        Y3g[(((size_t)c * MXY + (r >> 4)) * MXY + (2 * kyp + hh)) * 16 + (r & 15)];
  }
  __syncthreads();

  float2 E[16], O[16];
#pragma unroll
  for (int z = 0; z < 16; z++) { E[z] = make_float2(0.f, 0.f); O[z] = make_float2(0.f, 0.f); }

  int p = 0;
#pragma unroll 2
  for (int kx = 0; kx < 16; kx += 2) {
    float2 te = Tml[p];
    int p2 = p + x; if (p2 >= NSZ) p2 -= NSZ;
    float2 to = Tml[p2];
    p = p2 + x; if (p >= NSZ) p -= NSZ;
    const float4* ye = (const float4*)&ysd[h][kx][0];
    const float4* yo = (const float4*)&ysd[h][kx + 1][0];
#pragma unroll
    for (int qq = 0; qq < 8; qq++) {
      float4 a = ye[qq], b = yo[qq];
      E[2*qq].x   += te.x*a.x - te.y*a.y;  E[2*qq].y   += te.x*a.y + te.y*a.x;
      E[2*qq+1].x += te.x*a.z - te.y*a.w;  E[2*qq+1].y += te.x*a.w + te.y*a.z;
      O[2*qq].x   += to.x*b.x - to.y*b.y;  O[2*qq].y   += to.x*b.y + to.y*b.x;
      O[2*qq+1].x += to.x*b.z - to.y*b.w;  O[2*qq+1].y += to.x*b.w + to.y*b.z;
    }
  }
  p = (176 * x) % NSZ;
#pragma unroll 2
  for (int kx = 16; kx < 32; kx += 2) {
    float2 te = Tml[p];
    int p2 = p + x; if (p2 >= NSZ) p2 -= NSZ;
    float2 to = Tml[p2];
    p = p2 + x; if (p >= NSZ) p -= NSZ;
    const float4* ye = (const float4*)&ysd[h][kx][0];
    const float4* yo = (const float4*)&ysd[h][kx + 1][0];
#pragma unroll
    for (int qq = 0; qq < 8; qq++) {
      float4 a = ye[qq], b = yo[qq];
      E[2*qq].x   += te.x*a.x - te.y*a.y;  E[2*qq].y   += te.x*a.y + te.y*a.x;
      E[2*qq+1].x += te.x*a.z - te.y*a.w;  E[2*qq+1].y += te.x*a.w + te.y*a.z;
      O[2*qq].x   += to.x*b.x - to.y*b.y;  O[2*qq].y   += to.x*b.y + to.y*b.x;
      O[2*qq+1].x += to.x*b.z - to.y*b.w;  O[2*qq+1].y += to.x*b.w + to.y*b.z;
    }
  }

  float4* d0 = (float4*)&Y2g[(((size_t)c * NSZ + x) * MXY + ky) * 16];
  float4* d1 = (float4*)&Y2g[(((size_t)c * NSZ + x + 96) * MXY + ky) * 16];
#pragma unroll
  for (int qq = 0; qq < 8; qq++) {
    d0[qq] = make_float4(E[2*qq].x + O[2*qq].x,   E[2*qq].y + O[2*qq].y,
                         E[2*qq+1].x + O[2*qq+1].x, E[2*qq+1].y + O[2*qq+1].y);
    d1[qq] = make_float4(E[2*qq].x - O[2*qq].x,   E[2*qq].y - O[2*qq].y,
                         E[2*qq+1].x - O[2*qq+1].x, E[2*qq+1].y - O[2*qq+1].y);
  }
}

// ---------------- I2: inverse y (32 modes -> 192 y), even/odd folded ---------
__global__ void __launch_bounds__(192) k_i2() {
  __shared__ __align__(16) float2 ysd[2][32][16];
  __shared__ float2 Tml[NSZ];
  int tid = threadIdx.x;
  int h = tid / 96, y = tid % 96;
  size_t line = (size_t)blockIdx.x * 2 + h;

  for (int i = tid; i < NSZ; i += 192) Tml[i] = Tm[i];
  for (int i = tid; i < 1024; i += 192) {
    int hh = i >> 9, r = i & 511;
    ysd[hh][r >> 4][r & 15] = Y2g[((size_t)blockIdx.x * 2 + hh) * 512 + r];
  }
  __syncthreads();

  float2 E[16], O[16];
#pragma unroll
  for (int z = 0; z < 16; z++) { E[z] = make_float2(0.f, 0.f); O[z] = make_float2(0.f, 0.f); }

  int p = 0;
#pragma unroll 2
  for (int ky = 0; ky < 16; ky += 2) {
    float2 te = Tml[p];
    int p2 = p + y; if (p2 >= NSZ) p2 -= NSZ;
    float2 to = Tml[p2];
    p = p2 + y; if (p >= NSZ) p -= NSZ;
    const float4* ye = (const float4*)&ysd[h][ky][0];
    const float4* yo = (const float4*)&ysd[h][ky + 1][0];
#pragma unroll
    for (int qq = 0; qq < 8; qq++) {
      float4 a = ye[qq], b = yo[qq];
      E[2*qq].x   += te.x*a.x - te.y*a.y;  E[2*qq].y   += te.x*a.y + te.y*a.x;
      E[2*qq+1].x += te.x*a.z - te.y*a.w;  E[2*qq+1].y += te.x*a.w + te.y*a.z;
      O[2*qq].x   += to.x*b.x - to.y*b.y;  O[2*qq].y   += to.x*b.y + to.y*b.x;
      O[2*qq+1].x += to.x*b.z - to.y*b.w;  O[2*qq+1].y += to.x*b.w + to.y*b.z;
    }
  }
  p = (176 * y) % NSZ;
#pragma unroll 2
  for (int ky = 16; ky < 32; ky += 2) {
    float2 te = Tml[p];
    int p2 = p + y; if (p2 >= NSZ) p2 -= NSZ;
    float2 to = Tml[p2];
    p = p2 + y; if (p >= NSZ) p -= NSZ;
    const float4* ye = (const float4*)&ysd[h][ky][0];
    const float4* yo = (const float4*)&ysd[h][ky + 1][0];
#pragma unroll
    for (int qq = 0; qq < 8; qq++) {
      float4 a = ye[qq], b = yo[qq];
      E[2*qq].x   += te.x*a.x - te.y*a.y;  E[2*qq].y   += te.x*a.y + te.y*a.x;
      E[2*qq+1].x += te.x*a.z - te.y*a.w;  E[2*qq+1].y += te.x*a.w + te.y*a.z;
      O[2*qq].x   += to.x*b.x - to.y*b.y;  O[2*qq].y   += to.x*b.y + to.y*b.x;
      O[2*qq+1].x += to.x*b.z - to.y*b.w;  O[2*qq+1].y += to.x*b.w + to.y*b.z;
    }
  }

  float4* d0 = (float4*)&Y1g[(line * NSZ + y) * 16];
  float4* d1 = (float4*)&Y1g[(line * NSZ + y + 96) * 16];
#pragma unroll
  for (int qq = 0; qq < 8; qq++) {
    d0[qq] = make_float4(E[2*qq].x + O[2*qq].x,   E[2*qq].y + O[2*qq].y,
                         E[2*qq+1].x + O[2*qq+1].x, E[2*qq+1].y + O[2*qq+1].y);
    d1[qq] = make_float4(E[2*qq].x - O[2*qq].x,   E[2*qq].y - O[2*qq].y,
                         E[2*qq+1].x - O[2*qq+1].x, E[2*qq+1].y - O[2*qq+1].y);
  }
}

// ---------------- I3: inverse z C2R as tf32 GEMM  out = Y1 @ Bi ---------------
// block: 256 thr = 8 warps (2 row-tiles x 4 col-tiles); 32 rows x 192 cols (3 grp)
__global__ void __launch_bounds__(256) k_i3(float* __restrict__ out) {
  __shared__ float Bs[192 * 32];                 // 24 KB, col-major Bs[z*32+k]
  __shared__ __align__(16) float As[32][40];     // 5.1 KB
  int tid = threadIdx.x;
  int wid = tid >> 5;
  int wr = wid >> 2, wc = wid & 3;
  size_t rowBase = (size_t)blockIdx.x * 32;

  for (int i = tid; i < 192 * 32; i += 256) Bs[i] = Bif[i];
  {
    int row = tid >> 3, u = tid & 7;   // 256 thr = 32 rows x 8 float4
    ((float4*)&As[row][0])[u] = ((const float4*)&Y1g[(rowBase + row) * 16])[u];
  }
  __syncthreads();

#pragma unroll
  for (int zg = 0; zg < 3; zg++) {
    wmma::fragment<wmma::accumulator, 16, 16, 8, float> acc;
    wmma::fill_fragment(acc, 0.0f);
    int zbase = zg * 64 + wc * 16;
#pragma unroll
    for (int k0 = 0; k0 < 32; k0 += 8) {
      wmma::fragment<wmma::matrix_a, 16, 16, 8, wmma::precision::tf32, wmma::row_major> af;
      wmma::fragment<wmma::matrix_b, 16, 16, 8, wmma::precision::tf32, wmma::col_major> bf;
      wmma::load_matrix_sync(af, &As[wr * 16][k0], 40);
      wmma::load_matrix_sync(bf, &Bs[zbase * 32 + k0], 32);
#pragma unroll
      for (int t = 0; t < af.num_elements; t++) af.x[t] = wmma::__float_to_tf32(af.x[t]);
#pragma unroll
      for (int t = 0; t < bf.num_elements; t++) bf.x[t] = wmma::__float_to_tf32(bf.x[t]);
      wmma::mma_sync(acc, af, bf, acc);
    }
    wmma::store_matrix_sync(out + (rowBase + wr * 16) * NSZ + zbase, acc, NSZ,
                            wmma::mem_row_major);
  }
}

// ---------------- launch -------------------------------------------------------
extern "C" void kernel_launch(void* const* d_in, const int* in_sizes, int n_in,
                              void* d_out, int out_size) {
  (void)in_sizes; (void)n_in; (void)out_size;
  const float* x  = (const float*)d_in[0];
  const float* wr = (const float*)d_in[1];
  const float* wi = (const float*)d_in[2];

  k_init<<<1, 256>>>();
  k_s1 <<<NROW / 64, 256>>>(x);             // 9216 blocks (tf32 WMMA)
  k_s2 <<<NLINE / 4, 128>>>();              // 768 blocks
  k_s3 <<<NC * MXY, 256>>>();               // 512 blocks
  k_mix<<<MXY * MXY, 256>>>(wr, wi);        // 1024 blocks
  k_i1 <<<NC * 16, 192>>>();                // 256 blocks
  k_i2 <<<NLINE / 2, 192>>>();              // 1536 blocks
  k_i3 <<<NROW / 32, 256>>>((float*)d_out); // 18432 blocks (tf32 WMMA)
}